// round 7
// baseline (speedup 1.0000x reference)
#include <cuda_runtime.h>
#include <cuda_bf16.h>
#include <math.h>
#include <stdint.h>

#define N_TOK 4096
#define EMBED 1024
#define NHEAD 16
#define HDIM 64
#define FFN 4096
#define QKV3 3072

// ---------------- scratch (device globals; no cudaMalloc allowed) ----------
__device__ alignas(16) float g_qkv[N_TOK * QKV3];
__device__ alignas(16) float g_attn[N_TOK * EMBED];
__device__ alignas(16) float g_res1[N_TOK * EMBED];
__device__ alignas(16) float g_h[N_TOK * EMBED];
__device__ alignas(16) float g_ffn[N_TOK * FFN];
__device__ alignas(16) float g_feats_a[N_TOK * EMBED];
__device__ alignas(16) float g_wqkv[EMBED * QKV3];
__device__ alignas(16) float g_wo[EMBED * EMBED];
__device__ alignas(16) float g_w1[EMBED * FFN];
__device__ alignas(16) float g_w2[FFN * EMBED];

__device__ __forceinline__ uint32_t f2tf32(float x) {
    uint32_t u;
    asm("cvt.rna.tf32.f32 %0, %1;" : "=r"(u) : "f"(x));
    return u;
}

__global__ void copy_tf32_kernel(const float* __restrict__ src,
                                 float* __restrict__ dst, int n) {
    int i = blockIdx.x * blockDim.x + threadIdx.x;
    if (i < n) dst[i] = __uint_as_float(f2tf32(src[i]));
}

// ---------------- TF32 tensor-core GEMM, templated BN, 3-stage pipeline ----
#define NSTAGE 3
#define BM 128
#define BK 32
#define ASTRIDE 36                       // 32 + 4 pad; bank(4g+t) conflict-free

template <int BNT> struct GemmCfg {
    static constexpr int BSTRIDE = BNT + 8;   // %32==8 -> bank(8t+g) conflict-free
    static constexpr int A_TILE = BM * ASTRIDE;
    static constexpr int B_TILE = BK * BSTRIDE;
    static constexpr int STAGE_FLOATS = A_TILE + B_TILE;
    static constexpr int SMEM_BYTES = NSTAGE * STAGE_FLOATS * 4;
    static constexpr int NT = BNT / 32;       // b-fragments per warp
};

__device__ __forceinline__ void cp16(uint32_t s, const void* g) {
    asm volatile("cp.async.cg.shared.global [%0], [%1], 16;" :: "r"(s), "l"(g));
}
__device__ __forceinline__ void cp_commit() {
    asm volatile("cp.async.commit_group;");
}
__device__ __forceinline__ void cp_wait1() {
    asm volatile("cp.async.wait_group 1;");
}

__device__ __forceinline__ void mma_tf32(float* c, const uint32_t* a, const uint32_t* b) {
    asm volatile(
        "mma.sync.aligned.m16n8k8.row.col.f32.tf32.tf32.f32 "
        "{%0,%1,%2,%3}, {%4,%5,%6,%7}, {%8,%9}, {%0,%1,%2,%3};"
        : "+f"(c[0]), "+f"(c[1]), "+f"(c[2]), "+f"(c[3])
        : "r"(a[0]), "r"(a[1]), "r"(a[2]), "r"(a[3]), "r"(b[0]), "r"(b[1]));
}

// EPI: 0 = bias, 1 = bias + resid, 2 = bias + gelu
template <int EPI, int BNT>
__global__ void __launch_bounds__(256, 1)
gemm_tc_kernel(const float* __restrict__ A, const float* __restrict__ W,
               const float* __restrict__ bias, const float* __restrict__ resid,
               float* __restrict__ C, int M, int N, int K) {
    using CFG = GemmCfg<BNT>;
    constexpr int NT = CFG::NT;
    constexpr int BSTRIDE = CFG::BSTRIDE;
    extern __shared__ float smem[];
    const uint32_t smem_base = (uint32_t)__cvta_generic_to_shared(smem);

    const int tid = threadIdx.x;
    const int wid = tid >> 5;
    const int lane = tid & 31;
    const int g = lane >> 2;
    const int t = lane & 3;
    const int m0 = blockIdx.y * BM;
    const int n0 = blockIdx.x * BNT;
    const int wm = (wid & 1) * 64;            // 2 warps over M
    const int wn = (wid >> 1) * (NT * 8);     // 4 warps over N

    const int NK = K >> 5;

    auto load_tile = [&](int s, int kt) {
        int k0 = kt * BK;
        uint32_t sb = smem_base + (uint32_t)(s * CFG::STAGE_FLOATS) * 4u;
#pragma unroll
        for (int i = 0; i < 4; i++) {
            int idx = tid + i * 256;
            int ar = idx >> 3, ac4 = idx & 7;
            cp16(sb + (uint32_t)(ar * ASTRIDE + ac4 * 4) * 4u,
                 &A[(size_t)(m0 + ar) * K + k0 + ac4 * 4]);
        }
        uint32_t sbB = sb + (uint32_t)CFG::A_TILE * 4u;
        constexpr int BC4 = BNT / 4;                 // float4 per B row
        constexpr int NB = BK * BC4 / 256;           // per-thread B loads
#pragma unroll
        for (int i = 0; i < NB; i++) {
            int idx = tid + i * 256;
            int br = idx / BC4, bc4 = idx % BC4;
            cp16(sbB + (uint32_t)(br * BSTRIDE + bc4 * 4) * 4u,
                 &W[(size_t)(k0 + br) * N + n0 + bc4 * 4]);
        }
    };

    float acc[4][NT][4];
#pragma unroll
    for (int i = 0; i < 4; i++)
#pragma unroll
        for (int j = 0; j < NT; j++)
#pragma unroll
            for (int r = 0; r < 4; r++) acc[i][j][r] = 0.f;

    load_tile(0, 0); cp_commit();
    load_tile(1, 1); cp_commit();

    for (int k = 0; k < NK; k++) {
        cp_wait1();
        __syncthreads();
        if (k + 2 < NK) load_tile((k + 2) % NSTAGE, k + 2);
        cp_commit();

        const float* As_ = smem + (k % NSTAGE) * CFG::STAGE_FLOATS;
        const float* Bs_ = As_ + CFG::A_TILE;
#pragma unroll
        for (int ks = 0; ks < 4; ks++) {
            uint32_t a[4][4];
#pragma unroll
            for (int mt = 0; mt < 4; mt++) {
                int r = wm + mt * 16 + g;
                int c = ks * 8 + t;
                a[mt][0] = __float_as_uint(As_[r * ASTRIDE + c]);
                a[mt][1] = __float_as_uint(As_[(r + 8) * ASTRIDE + c]);
                a[mt][2] = __float_as_uint(As_[r * ASTRIDE + c + 4]);
                a[mt][3] = __float_as_uint(As_[(r + 8) * ASTRIDE + c + 4]);
            }
            uint32_t b[NT][2];
#pragma unroll
            for (int nt = 0; nt < NT; nt++) {
                int c = wn + nt * 8 + g;
                b[nt][0] = __float_as_uint(Bs_[(ks * 8 + t) * BSTRIDE + c]);
                b[nt][1] = __float_as_uint(Bs_[(ks * 8 + t + 4) * BSTRIDE + c]);
            }
#pragma unroll
            for (int mt = 0; mt < 4; mt++)
#pragma unroll
                for (int nt = 0; nt < NT; nt++)
                    mma_tf32(acc[mt][nt], a[mt], b[nt]);
        }
        __syncthreads();
    }

#pragma unroll
    for (int mt = 0; mt < 4; mt++) {
#pragma unroll
        for (int nt = 0; nt < NT; nt++) {
            int r0 = m0 + wm + mt * 16 + g;
            int c0 = n0 + wn + nt * 8 + 2 * t;
#pragma unroll
            for (int half = 0; half < 2; half++) {
                int r = r0 + half * 8;
#pragma unroll
                for (int e = 0; e < 2; e++) {
                    int c = c0 + e;
                    float v = acc[mt][nt][half * 2 + e] + bias[c];
                    if (EPI == 1) v += resid[(size_t)r * N + c];
                    if (EPI == 2) {
                        float x = v;
                        float th = tanhf(0.7978845608028654f *
                                         (x + 0.044715f * x * x * x));
                        v = 0.5f * x * (1.f + th);
                    }
                    C[(size_t)r * N + c] = v;
                }
            }
        }
    }
}

// ---------------- RoPE (in-place on q,k of g_qkv) --------------------------
__global__ void rope_kernel(float* __restrict__ qkv, const float* __restrict__ coords,
                            const float* __restrict__ inv_freq) {
    int n = blockIdx.x;
    __shared__ alignas(16) float cs[32];
    __shared__ alignas(16) float sn[32];
    int t = threadIdx.x;
    if (t < 32) {
        int d = t >> 3, f = t & 7;
        float ang = coords[n * 4 + d] * inv_freq[d * 8 + f];
        cs[t] = cosf(ang);
        sn[t] = sinf(ang);
    }
    __syncthreads();
#pragma unroll
    for (int w = t; w < 1024; w += 256) {
        int qk = w >> 9;
        int h = (w >> 5) & 15;
        int p = w & 31;
        float* base = qkv + (size_t)n * QKV3 + qk * EMBED + h * HDIM;
        float x1 = base[p], x2 = base[p + 32];
        base[p]      = x1 * cs[p] - x2 * sn[p];
        base[p + 32] = x2 * cs[p] + x1 * sn[p];
    }
}

// ---------------- Flash attention, split-d (2 threads per query) -----------
// grid: (N_TOK/64, NHEAD), block: 128 threads.
// thread pair (2q, 2q+1) handles query q; dh = tid&1 selects 32-dim half.
// Partner is lane^1 (same warp): score = partial + shfl_xor(partial, 1).
__global__ void __launch_bounds__(128)
attn_kernel(const float* __restrict__ qkv, const int* __restrict__ cu,
            float* __restrict__ out) {
    const int h = blockIdx.y;
    const int tid = threadIdx.x;
    const int qloc = tid >> 1;
    const int dh = tid & 1;
    const int qi = blockIdx.x * 64 + qloc;

    int s = 0;
#pragma unroll
    for (int i = 1; i <= 7; i++)
        if (cu[i] <= qi) s = i;
    const int kstart = cu[s];
    const int kend = cu[s + 1];

    __shared__ int skb, ske;
    if (tid == 0) { skb = kstart; ske = kend; }
    __syncthreads();
    atomicMin(&skb, kstart);
    atomicMax(&ske, kend);
    __syncthreads();
    const int kb0 = skb & ~63;
    const int keM = ske;

    __shared__ alignas(16) float Ks[64 * 64];
    __shared__ alignas(16) float Vs[64 * 64];

    float q[32], o[32];
    {
        const float* qp = qkv + (size_t)qi * QKV3 + h * HDIM + dh * 32;
#pragma unroll
        for (int d = 0; d < 32; d++) {
            q[d] = qp[d] * 0.125f;   // 1/sqrt(64)
            o[d] = 0.f;
        }
    }
    float m = -1e30f, l = 0.f;

    for (int kt = kb0; kt < keM; kt += 64) {
        {
            // row tok = kt + qloc; thread pair splits the 64-float row
            int tok = kt + qloc;
            const float* kp = qkv + (size_t)tok * QKV3 + EMBED + h * HDIM + dh * 32;
            const float* vp = qkv + (size_t)tok * QKV3 + 2 * EMBED + h * HDIM + dh * 32;
            float4* kd = (float4*)&Ks[qloc * 64 + dh * 32];
            float4* vd = (float4*)&Vs[qloc * 64 + dh * 32];
#pragma unroll
            for (int d4 = 0; d4 < 8; d4++) {
                kd[d4] = ((const float4*)kp)[d4];
                vd[d4] = ((const float4*)vp)[d4];
            }
        }
        __syncthreads();

#pragma unroll 1
        for (int jc = 0; jc < 64; jc += 16) {
            float sc[16];
#pragma unroll
            for (int jj = 0; jj < 16; jj++) {
                const float4* kr = (const float4*)&Ks[(jc + jj) * 64 + dh * 32];
                float a0 = 0.f, a1 = 0.f, a2 = 0.f, a3 = 0.f;
#pragma unroll
                for (int d4 = 0; d4 < 8; d4++) {
                    float4 kv = kr[d4];
                    a0 = fmaf(q[d4 * 4 + 0], kv.x, a0);
                    a1 = fmaf(q[d4 * 4 + 1], kv.y, a1);
                    a2 = fmaf(q[d4 * 4 + 2], kv.z, a2);
                    a3 = fmaf(q[d4 * 4 + 3], kv.w, a3);
                }
                float partial = (a0 + a1) + (a2 + a3);
                float full = partial + __shfl_xor_sync(0xffffffffu, partial, 1);
                int kg = kt + jc + jj;
                bool valid = (kg >= kstart) && (kg < kend);
                sc[jj] = valid ? full : -1e30f;
            }
            float cm = -1e30f;
#pragma unroll
            for (int jj = 0; jj < 16; jj++) cm = fmaxf(cm, sc[jj]);
            float mn = fmaxf(m, cm);
            float scale = expf(m - mn);
            l *= scale;
#pragma unroll
            for (int d = 0; d < 32; d++) o[d] *= scale;
            float p[16];
            float ps = 0.f;
#pragma unroll
            for (int jj = 0; jj < 16; jj++) {
                int kg = kt + jc + jj;
                bool valid = (kg >= kstart) && (kg < kend);
                p[jj] = valid ? expf(sc[jj] - mn) : 0.f;
                ps += p[jj];
            }
            l += ps;
            m = mn;
#pragma unroll
            for (int d4 = 0; d4 < 8; d4++) {
                float o0 = o[d4 * 4 + 0], o1 = o[d4 * 4 + 1];
                float o2 = o[d4 * 4 + 2], o3 = o[d4 * 4 + 3];
#pragma unroll
                for (int jj = 0; jj < 16; jj++) {
                    float4 vv = *(const float4*)&Vs[(jc + jj) * 64 + dh * 32 + d4 * 4];
                    o0 = fmaf(p[jj], vv.x, o0);
                    o1 = fmaf(p[jj], vv.y, o1);
                    o2 = fmaf(p[jj], vv.z, o2);
                    o3 = fmaf(p[jj], vv.w, o3);
                }
                o[d4 * 4 + 0] = o0; o[d4 * 4 + 1] = o1;
                o[d4 * 4 + 2] = o2; o[d4 * 4 + 3] = o3;
            }
        }
        __syncthreads();
    }

    float inv_l = 1.f / l;
    float* op = out + (size_t)qi * EMBED + h * HDIM + dh * 32;
#pragma unroll
    for (int d = 0; d < 32; d++) op[d] = o[d] * inv_l;
}

// ---------------- LayerNorm ------------------------------------------------
__device__ __forceinline__ float blockReduceSum(float v) {
    __shared__ alignas(16) float red[8];
    int lane = threadIdx.x & 31, wid = threadIdx.x >> 5;
#pragma unroll
    for (int off = 16; off; off >>= 1) v += __shfl_xor_sync(0xffffffffu, v, off);
    __syncthreads();
    if (lane == 0) red[wid] = v;
    __syncthreads();
    v = (threadIdx.x < 8) ? red[threadIdx.x] : 0.f;
    if (wid == 0) {
#pragma unroll
        for (int off = 4; off; off >>= 1) v += __shfl_xor_sync(0xffu, v, off);
        if (lane == 0) red[0] = v;
    }
    __syncthreads();
    return red[0];
}

__global__ void __launch_bounds__(256)
layernorm_kernel(const float* __restrict__ x, const float* __restrict__ g,
                 const float* __restrict__ b, float* __restrict__ y) {
    int row = blockIdx.x;
    int t = threadIdx.x;
    const float4* xr = (const float4*)(x + (size_t)row * EMBED);
    float4 v = xr[t];
    float s = (v.x + v.y) + (v.z + v.w);
    float mean = blockReduceSum(s) * (1.f / 1024.f);
    float dx = v.x - mean, dy = v.y - mean, dz = v.z - mean, dw = v.w - mean;
    float sq = dx * dx + dy * dy + dz * dz + dw * dw;
    float var = blockReduceSum(sq) * (1.f / 1024.f);
    float rstd = rsqrtf(var + 1e-5f);
    int c = t * 4;
    float g0 = g[c], g1 = g[c + 1], g2 = g[c + 2], g3 = g[c + 3];
    float b0 = b[c], b1 = b[c + 1], b2 = b[c + 2], b3 = b[c + 3];
    float* yr = y + (size_t)row * EMBED + c;
    yr[0] = dx * rstd * g0 + b0;
    yr[1] = dy * rstd * g1 + b1;
    yr[2] = dz * rstd * g2 + b2;
    yr[3] = dw * rstd * g3 + b3;
}

// ---------------- launch ---------------------------------------------------
extern "C" void kernel_launch(void* const* d_in, const int* in_sizes, int n_in,
                              void* d_out, int out_size) {
    const float* coords   = (const float*)d_in[0];
    const float* feats    = (const float*)d_in[1];
    const int*   cu       = (const int*)d_in[2];
    const float* Wqkv     = (const float*)d_in[3];
    const float* bqkv     = (const float*)d_in[4];
    const float* Wo       = (const float*)d_in[5];
    const float* bo       = (const float*)d_in[6];
    const float* inv_freq = (const float*)d_in[7];
    const float* ln1_g    = (const float*)d_in[8];
    const float* ln1_b    = (const float*)d_in[9];
    const float* W1       = (const float*)d_in[10];
    const float* b1       = (const float*)d_in[11];
    const float* W2       = (const float*)d_in[12];
    const float* b2       = (const float*)d_in[13];
    const float* ln2_g    = (const float*)d_in[14];
    const float* ln2_b    = (const float*)d_in[15];
    float* out = (float*)d_out;

    float *qkv, *attn, *res1, *h, *ffn;
    float *feats_a, *wqkv_a, *wo_a, *w1_a, *w2_a;
    cudaGetSymbolAddress((void**)&qkv, g_qkv);
    cudaGetSymbolAddress((void**)&attn, g_attn);
    cudaGetSymbolAddress((void**)&res1, g_res1);
    cudaGetSymbolAddress((void**)&h, g_h);
    cudaGetSymbolAddress((void**)&ffn, g_ffn);
    cudaGetSymbolAddress((void**)&feats_a, g_feats_a);
    cudaGetSymbolAddress((void**)&wqkv_a, g_wqkv);
    cudaGetSymbolAddress((void**)&wo_a, g_wo);
    cudaGetSymbolAddress((void**)&w1_a, g_w1);
    cudaGetSymbolAddress((void**)&w2_a, g_w2);

    constexpr int SM256 = GemmCfg<256>::SMEM_BYTES;
    constexpr int SM128 = GemmCfg<128>::SMEM_BYTES;
    cudaFuncSetAttribute(gemm_tc_kernel<0, 256>,
                         cudaFuncAttributeMaxDynamicSharedMemorySize, SM256);
    cudaFuncSetAttribute(gemm_tc_kernel<2, 256>,
                         cudaFuncAttributeMaxDynamicSharedMemorySize, SM256);
    cudaFuncSetAttribute(gemm_tc_kernel<1, 128>,
                         cudaFuncAttributeMaxDynamicSharedMemorySize, SM128);

    // 0. align + tf32-round unaligned inputs
    copy_tf32_kernel<<<(N_TOK * EMBED) / 256, 256>>>(feats, feats_a, N_TOK * EMBED);
    copy_tf32_kernel<<<(EMBED * QKV3) / 256, 256>>>(Wqkv, wqkv_a, EMBED * QKV3);
    copy_tf32_kernel<<<(EMBED * EMBED) / 256, 256>>>(Wo, wo_a, EMBED * EMBED);
    copy_tf32_kernel<<<(EMBED * FFN) / 256, 256>>>(W1, w1_a, EMBED * FFN);
    copy_tf32_kernel<<<(FFN * EMBED) / 256, 256>>>(W2, w2_a, FFN * EMBED);

    // 1. QKV projection (N=3072, BN=256)
    gemm_tc_kernel<0, 256><<<dim3(QKV3 / 256, N_TOK / BM), 256, SM256>>>(
        feats_a, wqkv_a, bqkv, nullptr, qkv, N_TOK, QKV3, EMBED);
    // 2. RoPE on q,k
    rope_kernel<<<N_TOK, 256>>>(qkv, coords, inv_freq);
    // 3. Segment attention (split-d)
    attn_kernel<<<dim3(N_TOK / 64, NHEAD), 128>>>(qkv, cu, attn);
    // 4. Wo projection + residual (N=1024, BN=128)
    gemm_tc_kernel<1, 128><<<dim3(EMBED / 128, N_TOK / BM), 256, SM128>>>(
        attn, wo_a, bo, feats, res1, N_TOK, EMBED, EMBED);
    // 5. LN1 -> h
    layernorm_kernel<<<N_TOK, 256>>>(res1, ln1_g, ln1_b, h);
    // 6. FFN up + gelu (N=4096, BN=256)
    gemm_tc_kernel<2, 256><<<dim3(FFN / 256, N_TOK / BM), 256, SM256>>>(
        h, w1_a, b1, nullptr, ffn, N_TOK, FFN, EMBED);
    // 7. FFN down + residual (N=1024, BN=128)
    gemm_tc_kernel<1, 128><<<dim3(EMBED / 128, N_TOK / BM), 256, SM128>>>(
        ffn, w2_a, b2, h, res1, N_TOK, EMBED, FFN);
    // 8. LN2 -> out
    layernorm_kernel<<<N_TOK, 256>>>(res1, ln2_g, ln2_b, out);
}

// round 12
// speedup vs baseline: 2.0413x; 2.0413x over previous
#include <cuda_runtime.h>
#include <cuda_bf16.h>
#include <math.h>
#include <stdint.h>

#define N_TOK 4096
#define EMBED 1024
#define NHEAD 16
#define HDIM 64
#define FFN 4096
#define QKV3 3072

// ---------------- scratch (device globals; no cudaMalloc allowed) ----------
__device__ alignas(16) float g_qkv[N_TOK * QKV3];
__device__ alignas(16) float g_attn[N_TOK * EMBED];
__device__ alignas(16) float g_res1[N_TOK * EMBED];
__device__ alignas(16) float g_h[N_TOK * EMBED];
__device__ alignas(16) float g_ffn[N_TOK * FFN];
__device__ alignas(16) float g_feats_a[N_TOK * EMBED];
__device__ alignas(16) float g_wqkv[EMBED * QKV3];
__device__ alignas(16) float g_wo[EMBED * EMBED];
__device__ alignas(16) float g_w1[EMBED * FFN];
__device__ alignas(16) float g_w2[FFN * EMBED];

__device__ __forceinline__ uint32_t f2tf32(float x) {
    uint32_t u;
    asm("cvt.rna.tf32.f32 %0, %1;" : "=r"(u) : "f"(x));
    return u;
}

__global__ void copy_tf32_kernel(const float* __restrict__ src,
                                 float* __restrict__ dst, int n) {
    int i = blockIdx.x * blockDim.x + threadIdx.x;
    if (i < n) dst[i] = __uint_as_float(f2tf32(src[i]));
}

// ---------------- TF32 tensor-core GEMM (R6 config: BN=256, 3-stage) -------
#define NSTAGE 3
#define BM 128
#define BN 256
#define BK 32
#define ASTRIDE 36     // 32 + 4 pad; bank(4g+t) conflict-free
#define BSTRIDE 264    // 256 + 8 pad; %32==8 -> bank(8t+g) conflict-free
#define A_TILE (BM * ASTRIDE)
#define B_TILE (BK * BSTRIDE)
#define STAGE_FLOATS (A_TILE + B_TILE)
#define GEMM_SMEM_BYTES (NSTAGE * STAGE_FLOATS * 4)

__device__ __forceinline__ void cp16(uint32_t s, const void* g) {
    asm volatile("cp.async.cg.shared.global [%0], [%1], 16;" :: "r"(s), "l"(g));
}
__device__ __forceinline__ void cp_commit() {
    asm volatile("cp.async.commit_group;");
}
__device__ __forceinline__ void cp_wait1() {
    asm volatile("cp.async.wait_group 1;");
}

__device__ __forceinline__ void mma_tf32(float* c, const uint32_t* a, const uint32_t* b) {
    asm volatile(
        "mma.sync.aligned.m16n8k8.row.col.f32.tf32.tf32.f32 "
        "{%0,%1,%2,%3}, {%4,%5,%6,%7}, {%8,%9}, {%0,%1,%2,%3};"
        : "+f"(c[0]), "+f"(c[1]), "+f"(c[2]), "+f"(c[3])
        : "r"(a[0]), "r"(a[1]), "r"(a[2]), "r"(a[3]), "r"(b[0]), "r"(b[1]));
}

// EPI: 0 = bias, 1 = bias + resid, 2 = bias + gelu
template <int EPI>
__global__ void __launch_bounds__(256, 1)
gemm_tc_kernel(const float* __restrict__ A, const float* __restrict__ W,
               const float* __restrict__ bias, const float* __restrict__ resid,
               float* __restrict__ C, int M, int N, int K) {
    extern __shared__ float smem[];
    const uint32_t smem_base = (uint32_t)__cvta_generic_to_shared(smem);

    const int tid = threadIdx.x;
    const int wid = tid >> 5;
    const int lane = tid & 31;
    const int g = lane >> 2;
    const int t = lane & 3;
    const int m0 = blockIdx.y * BM;
    const int n0 = blockIdx.x * BN;
    const int wm = (wid & 1) * 64;
    const int wn = (wid >> 1) * 64;

    const int NK = K >> 5;

    auto load_tile = [&](int s, int kt) {
        int k0 = kt * BK;
        uint32_t sb = smem_base + (uint32_t)(s * STAGE_FLOATS) * 4u;
#pragma unroll
        for (int i = 0; i < 4; i++) {
            int idx = tid + i * 256;
            int ar = idx >> 3, ac4 = idx & 7;
            cp16(sb + (uint32_t)(ar * ASTRIDE + ac4 * 4) * 4u,
                 &A[(size_t)(m0 + ar) * K + k0 + ac4 * 4]);
        }
        uint32_t sbB = sb + (uint32_t)A_TILE * 4u;
#pragma unroll
        for (int i = 0; i < 8; i++) {
            int idx = tid + i * 256;
            int br = idx >> 6, bc4 = idx & 63;
            cp16(sbB + (uint32_t)(br * BSTRIDE + bc4 * 4) * 4u,
                 &W[(size_t)(k0 + br) * N + n0 + bc4 * 4]);
        }
    };

    float acc[4][8][4];
#pragma unroll
    for (int i = 0; i < 4; i++)
#pragma unroll
        for (int j = 0; j < 8; j++)
#pragma unroll
            for (int r = 0; r < 4; r++) acc[i][j][r] = 0.f;

    load_tile(0, 0); cp_commit();
    load_tile(1, 1); cp_commit();

    for (int k = 0; k < NK; k++) {
        cp_wait1();
        __syncthreads();
        if (k + 2 < NK) load_tile((k + 2) % NSTAGE, k + 2);
        cp_commit();

        const float* As_ = smem + (k % NSTAGE) * STAGE_FLOATS;
        const float* Bs_ = As_ + A_TILE;
#pragma unroll
        for (int ks = 0; ks < 4; ks++) {
            uint32_t a[4][4];
#pragma unroll
            for (int mt = 0; mt < 4; mt++) {
                int r = wm + mt * 16 + g;
                int c = ks * 8 + t;
                a[mt][0] = __float_as_uint(As_[r * ASTRIDE + c]);
                a[mt][1] = __float_as_uint(As_[(r + 8) * ASTRIDE + c]);
                a[mt][2] = __float_as_uint(As_[r * ASTRIDE + c + 4]);
                a[mt][3] = __float_as_uint(As_[(r + 8) * ASTRIDE + c + 4]);
            }
            uint32_t b[8][2];
#pragma unroll
            for (int nt = 0; nt < 8; nt++) {
                int c = wn + nt * 8 + g;
                b[nt][0] = __float_as_uint(Bs_[(ks * 8 + t) * BSTRIDE + c]);
                b[nt][1] = __float_as_uint(Bs_[(ks * 8 + t + 4) * BSTRIDE + c]);
            }
#pragma unroll
            for (int mt = 0; mt < 4; mt++)
#pragma unroll
                for (int nt = 0; nt < 8; nt++)
                    mma_tf32(acc[mt][nt], a[mt], b[nt]);
        }
        __syncthreads();
    }

#pragma unroll
    for (int mt = 0; mt < 4; mt++) {
#pragma unroll
        for (int nt = 0; nt < 8; nt++) {
            int r0 = m0 + wm + mt * 16 + g;
            int c0 = n0 + wn + nt * 8 + 2 * t;
#pragma unroll
            for (int half = 0; half < 2; half++) {
                int r = r0 + half * 8;
#pragma unroll
                for (int e = 0; e < 2; e++) {
                    int c = c0 + e;
                    float v = acc[mt][nt][half * 2 + e] + bias[c];
                    if (EPI == 1) v += resid[(size_t)r * N + c];
                    if (EPI == 2) {
                        float x = v;
                        float th = tanhf(0.7978845608028654f *
                                         (x + 0.044715f * x * x * x));
                        v = 0.5f * x * (1.f + th);
                    }
                    C[(size_t)r * N + c] = v;
                }
            }
        }
    }
}

// ---------------- RoPE (in-place on q,k of g_qkv) --------------------------
__global__ void rope_kernel(float* __restrict__ qkv, const float* __restrict__ coords,
                            const float* __restrict__ inv_freq) {
    int n = blockIdx.x;
    __shared__ alignas(16) float cs[32];
    __shared__ alignas(16) float sn[32];
    int t = threadIdx.x;
    if (t < 32) {
        int d = t >> 3, f = t & 7;
        float ang = coords[n * 4 + d] * inv_freq[d * 8 + f];
        cs[t] = cosf(ang);
        sn[t] = sinf(ang);
    }
    __syncthreads();
#pragma unroll
    for (int w = t; w < 1024; w += 256) {
        int qk = w >> 9;
        int h = (w >> 5) & 15;
        int p = w & 31;
        float* base = qkv + (size_t)n * QKV3 + qk * EMBED + h * HDIM;
        float x1 = base[p], x2 = base[p + 32];
        base[p]      = x1 * cs[p] - x2 * sn[p];
        base[p + 32] = x2 * cs[p] + x1 * sn[p];
    }
}

// ---------------- FlashAttention with tf32 mma ------------------------------
// 64 queries x 64 keys per tile; 4 warps x 16 query rows; head dim 64.
// S = Q K^T via mma (K tile read transposed), online softmax in c-layout,
// P -> smem -> mma with V for O accumulation.
#define KS_STRIDE 76   // %32==12: transposed b-read bank (12g+t) all distinct
#define VS_STRIDE 72   // %32==8:  natural b-read bank (8t+g) all distinct
#define PS_STRIDE 68   // %32==4:  a-read bank (4g+t) all distinct
#define ATTN_SMEM_FLOATS (64 * KS_STRIDE + 64 * VS_STRIDE + 64 * PS_STRIDE)
#define ATTN_SMEM_BYTES (ATTN_SMEM_FLOATS * 4)

__global__ void __launch_bounds__(128, 1)
attn_mma_kernel(const float* __restrict__ qkv, const int* __restrict__ cu,
                float* __restrict__ out) {
    extern __shared__ float asmem[];
    float* Ks = asmem;                       // [64][KS_STRIDE]
    float* Vs = Ks + 64 * KS_STRIDE;         // [64][VS_STRIDE]
    float* Ps = Vs + 64 * VS_STRIDE;         // [64][PS_STRIDE]
    __shared__ int kst[64], ken[64];

    const int h = blockIdx.y;
    const int qb = blockIdx.x * 64;
    const int tid = threadIdx.x;
    const int wid = tid >> 5;
    const int lane = tid & 31;
    const int g = lane >> 2;
    const int t = lane & 3;
    const int r0 = wid * 16 + g;
    const int r1 = r0 + 8;

    if (tid < 64) {
        int qi = qb + tid;
        int s = 0;
#pragma unroll
        for (int i = 1; i <= 7; i++)
            if (cu[i] <= qi) s = i;
        kst[tid] = cu[s];
        ken[tid] = cu[s + 1];
    }
    __syncthreads();
    const int kb0 = kst[0] & ~63;    // cu sorted -> row 0 has min start
    const int keM = ken[63];         // row 63 has max end
    const int ks0 = kst[r0], ke0 = ken[r0];
    const int ks1 = kst[r1], ke1 = ken[r1];

    // Q fragments in registers (one-time scattered loads), pre-scaled
    uint32_t qf[8][4];
    {
        const float* q0 = qkv + (size_t)(qb + r0) * QKV3 + h * HDIM;
        const float* q1 = qkv + (size_t)(qb + r1) * QKV3 + h * HDIM;
#pragma unroll
        for (int ks = 0; ks < 8; ks++) {
            qf[ks][0] = __float_as_uint(q0[ks * 8 + t] * 0.125f);
            qf[ks][1] = __float_as_uint(q1[ks * 8 + t] * 0.125f);
            qf[ks][2] = __float_as_uint(q0[ks * 8 + t + 4] * 0.125f);
            qf[ks][3] = __float_as_uint(q1[ks * 8 + t + 4] * 0.125f);
        }
    }

    float O[8][4];
#pragma unroll
    for (int nt = 0; nt < 8; nt++)
#pragma unroll
        for (int e = 0; e < 4; e++) O[nt][e] = 0.f;
    float m0 = -1e30f, m1 = -1e30f, l0 = 0.f, l1 = 0.f;

    for (int kt = kb0; kt < keM; kt += 64) {
        __syncthreads();   // protect prior-iteration Vs reads
        {
            int row = tid >> 1, cb = (tid & 1) * 32;
            const float* kp = qkv + (size_t)(kt + row) * QKV3 + EMBED + h * HDIM + cb;
            const float* vp = qkv + (size_t)(kt + row) * QKV3 + 2 * EMBED + h * HDIM + cb;
            float4* kd = (float4*)&Ks[row * KS_STRIDE + cb];
            float4* vd = (float4*)&Vs[row * VS_STRIDE + cb];
#pragma unroll
            for (int d4 = 0; d4 < 8; d4++) {
                kd[d4] = ((const float4*)kp)[d4];
                vd[d4] = ((const float4*)vp)[d4];
            }
        }
        __syncthreads();

        // S = Q K^T   (b-frag: B[d][key] = Ks[key][d], read transposed)
        float S[8][4];
#pragma unroll
        for (int nt = 0; nt < 8; nt++)
#pragma unroll
            for (int e = 0; e < 4; e++) S[nt][e] = 0.f;
#pragma unroll
        for (int ks = 0; ks < 8; ks++) {
#pragma unroll
            for (int nt = 0; nt < 8; nt++) {
                uint32_t b[2];
                b[0] = __float_as_uint(Ks[(nt * 8 + g) * KS_STRIDE + ks * 8 + t]);
                b[1] = __float_as_uint(Ks[(nt * 8 + g) * KS_STRIDE + ks * 8 + t + 4]);
                mma_tf32(S[nt], qf[ks], b);
            }
        }

        // mask + online softmax (rows r0, r1; cols nt*8 + 2t + {0,1})
        float cm0 = -1e30f, cm1 = -1e30f;
#pragma unroll
        for (int nt = 0; nt < 8; nt++) {
            int c0 = kt + nt * 8 + 2 * t;
            int c1 = c0 + 1;
            S[nt][0] = (c0 >= ks0 && c0 < ke0) ? S[nt][0] : -1e30f;
            S[nt][1] = (c1 >= ks0 && c1 < ke0) ? S[nt][1] : -1e30f;
            S[nt][2] = (c0 >= ks1 && c0 < ke1) ? S[nt][2] : -1e30f;
            S[nt][3] = (c1 >= ks1 && c1 < ke1) ? S[nt][3] : -1e30f;
            cm0 = fmaxf(cm0, fmaxf(S[nt][0], S[nt][1]));
            cm1 = fmaxf(cm1, fmaxf(S[nt][2], S[nt][3]));
        }
        cm0 = fmaxf(cm0, __shfl_xor_sync(0xffffffffu, cm0, 1));
        cm0 = fmaxf(cm0, __shfl_xor_sync(0xffffffffu, cm0, 2));
        cm1 = fmaxf(cm1, __shfl_xor_sync(0xffffffffu, cm1, 1));
        cm1 = fmaxf(cm1, __shfl_xor_sync(0xffffffffu, cm1, 2));
        float mn0 = fmaxf(m0, cm0);
        float mn1 = fmaxf(m1, cm1);
        float sc0 = __expf(m0 - mn0);
        float sc1 = __expf(m1 - mn1);

        float ps0 = 0.f, ps1 = 0.f;
#pragma unroll
        for (int nt = 0; nt < 8; nt++) {
            float p00 = (S[nt][0] > -1e29f) ? __expf(S[nt][0] - mn0) : 0.f;
            float p01 = (S[nt][1] > -1e29f) ? __expf(S[nt][1] - mn0) : 0.f;
            float p10 = (S[nt][2] > -1e29f) ? __expf(S[nt][2] - mn1) : 0.f;
            float p11 = (S[nt][3] > -1e29f) ? __expf(S[nt][3] - mn1) : 0.f;
            ps0 += p00 + p01;
            ps1 += p10 + p11;
            Ps[r0 * PS_STRIDE + nt * 8 + 2 * t]     = p00;
            Ps[r0 * PS_STRIDE + nt * 8 + 2 * t + 1] = p01;
            Ps[r1 * PS_STRIDE + nt * 8 + 2 * t]     = p10;
            Ps[r1 * PS_STRIDE + nt * 8 + 2 * t + 1] = p11;
            O[nt][0] *= sc0; O[nt][1] *= sc0;
            O[nt][2] *= sc1; O[nt][3] *= sc1;
        }
        ps0 += __shfl_xor_sync(0xffffffffu, ps0, 1);
        ps0 += __shfl_xor_sync(0xffffffffu, ps0, 2);
        ps1 += __shfl_xor_sync(0xffffffffu, ps1, 1);
        ps1 += __shfl_xor_sync(0xffffffffu, ps1, 2);
        l0 = l0 * sc0 + ps0;
        l1 = l1 * sc1 + ps1;
        m0 = mn0; m1 = mn1;
        __syncwarp();   // Ps rows are warp-private; order STS before LDS

        // O += P V   (a-frag from Ps, b-frag from Vs natural layout)
#pragma unroll
        for (int ks2 = 0; ks2 < 8; ks2++) {
            uint32_t pa[4];
            pa[0] = __float_as_uint(Ps[r0 * PS_STRIDE + ks2 * 8 + t]);
            pa[1] = __float_as_uint(Ps[r1 * PS_STRIDE + ks2 * 8 + t]);
            pa[2] = __float_as_uint(Ps[r0 * PS_STRIDE + ks2 * 8 + t + 4]);
            pa[3] = __float_as_uint(Ps[r1 * PS_STRIDE + ks2 * 8 + t + 4]);
#pragma unroll
            for (int nt = 0; nt < 8; nt++) {
                uint32_t vb[2];
                vb[0] = __float_as_uint(Vs[(ks2 * 8 + t) * VS_STRIDE + nt * 8 + g]);
                vb[1] = __float_as_uint(Vs[(ks2 * 8 + t + 4) * VS_STRIDE + nt * 8 + g]);
                mma_tf32(O[nt], pa, vb);
            }
        }
        __syncwarp();
    }

    float il0 = 1.f / l0, il1 = 1.f / l1;
    float* o0 = out + (size_t)(qb + r0) * EMBED + h * HDIM;
    float* o1 = out + (size_t)(qb + r1) * EMBED + h * HDIM;
#pragma unroll
    for (int nt = 0; nt < 8; nt++) {
        o0[nt * 8 + 2 * t]     = O[nt][0] * il0;
        o0[nt * 8 + 2 * t + 1] = O[nt][1] * il0;
        o1[nt * 8 + 2 * t]     = O[nt][2] * il1;
        o1[nt * 8 + 2 * t + 1] = O[nt][3] * il1;
    }
}

// ---------------- LayerNorm ------------------------------------------------
__device__ __forceinline__ float blockReduceSum(float v) {
    __shared__ alignas(16) float red[8];
    int lane = threadIdx.x & 31, wid = threadIdx.x >> 5;
#pragma unroll
    for (int off = 16; off; off >>= 1) v += __shfl_xor_sync(0xffffffffu, v, off);
    __syncthreads();
    if (lane == 0) red[wid] = v;
    __syncthreads();
    v = (threadIdx.x < 8) ? red[threadIdx.x] : 0.f;
    if (wid == 0) {
#pragma unroll
        for (int off = 4; off; off >>= 1) v += __shfl_xor_sync(0xffu, v, off);
        if (lane == 0) red[0] = v;
    }
    __syncthreads();
    return red[0];
}

__global__ void __launch_bounds__(256)
layernorm_kernel(const float* __restrict__ x, const float* __restrict__ g,
                 const float* __restrict__ b, float* __restrict__ y) {
    int row = blockIdx.x;
    int t = threadIdx.x;
    const float4* xr = (const float4*)(x + (size_t)row * EMBED);
    float4 v = xr[t];
    float s = (v.x + v.y) + (v.z + v.w);
    float mean = blockReduceSum(s) * (1.f / 1024.f);
    float dx = v.x - mean, dy = v.y - mean, dz = v.z - mean, dw = v.w - mean;
    float sq = dx * dx + dy * dy + dz * dz + dw * dw;
    float var = blockReduceSum(sq) * (1.f / 1024.f);
    float rstd = rsqrtf(var + 1e-5f);
    int c = t * 4;
    float g0 = g[c], g1 = g[c + 1], g2 = g[c + 2], g3 = g[c + 3];
    float b0 = b[c], b1 = b[c + 1], b2 = b[c + 2], b3 = b[c + 3];
    float* yr = y + (size_t)row * EMBED + c;
    yr[0] = dx * rstd * g0 + b0;
    yr[1] = dy * rstd * g1 + b1;
    yr[2] = dz * rstd * g2 + b2;
    yr[3] = dw * rstd * g3 + b3;
}

// ---------------- launch ---------------------------------------------------
extern "C" void kernel_launch(void* const* d_in, const int* in_sizes, int n_in,
                              void* d_out, int out_size) {
    const float* coords   = (const float*)d_in[0];
    const float* feats    = (const float*)d_in[1];
    const int*   cu       = (const int*)d_in[2];
    const float* Wqkv     = (const float*)d_in[3];
    const float* bqkv     = (const float*)d_in[4];
    const float* Wo       = (const float*)d_in[5];
    const float* bo       = (const float*)d_in[6];
    const float* inv_freq = (const float*)d_in[7];
    const float* ln1_g    = (const float*)d_in[8];
    const float* ln1_b    = (const float*)d_in[9];
    const float* W1       = (const float*)d_in[10];
    const float* b1       = (const float*)d_in[11];
    const float* W2       = (const float*)d_in[12];
    const float* b2       = (const float*)d_in[13];
    const float* ln2_g    = (const float*)d_in[14];
    const float* ln2_b    = (const float*)d_in[15];
    float* out = (float*)d_out;

    float *qkv, *attn, *res1, *h, *ffn;
    float *feats_a, *wqkv_a, *wo_a, *w1_a, *w2_a;
    cudaGetSymbolAddress((void**)&qkv, g_qkv);
    cudaGetSymbolAddress((void**)&attn, g_attn);
    cudaGetSymbolAddress((void**)&res1, g_res1);
    cudaGetSymbolAddress((void**)&h, g_h);
    cudaGetSymbolAddress((void**)&ffn, g_ffn);
    cudaGetSymbolAddress((void**)&feats_a, g_feats_a);
    cudaGetSymbolAddress((void**)&wqkv_a, g_wqkv);
    cudaGetSymbolAddress((void**)&wo_a, g_wo);
    cudaGetSymbolAddress((void**)&w1_a, g_w1);
    cudaGetSymbolAddress((void**)&w2_a, g_w2);

    cudaFuncSetAttribute(gemm_tc_kernel<0>,
                         cudaFuncAttributeMaxDynamicSharedMemorySize, GEMM_SMEM_BYTES);
    cudaFuncSetAttribute(gemm_tc_kernel<1>,
                         cudaFuncAttributeMaxDynamicSharedMemorySize, GEMM_SMEM_BYTES);
    cudaFuncSetAttribute(gemm_tc_kernel<2>,
                         cudaFuncAttributeMaxDynamicSharedMemorySize, GEMM_SMEM_BYTES);
    cudaFuncSetAttribute(attn_mma_kernel,
                         cudaFuncAttributeMaxDynamicSharedMemorySize, ATTN_SMEM_BYTES);

    // 0. align + tf32-round unaligned inputs
    copy_tf32_kernel<<<(N_TOK * EMBED) / 256, 256>>>(feats, feats_a, N_TOK * EMBED);
    copy_tf32_kernel<<<(EMBED * QKV3) / 256, 256>>>(Wqkv, wqkv_a, EMBED * QKV3);
    copy_tf32_kernel<<<(EMBED * EMBED) / 256, 256>>>(Wo, wo_a, EMBED * EMBED);
    copy_tf32_kernel<<<(EMBED * FFN) / 256, 256>>>(W1, w1_a, EMBED * FFN);
    copy_tf32_kernel<<<(FFN * EMBED) / 256, 256>>>(W2, w2_a, FFN * EMBED);

    // 1. QKV projection
    gemm_tc_kernel<0><<<dim3(QKV3 / BN, N_TOK / BM), 256, GEMM_SMEM_BYTES>>>(
        feats_a, wqkv_a, bqkv, nullptr, qkv, N_TOK, QKV3, EMBED);
    // 2. RoPE on q,k
    rope_kernel<<<N_TOK, 256>>>(qkv, coords, inv_freq);
    // 3. FlashAttention (tf32 mma)
    attn_mma_kernel<<<dim3(N_TOK / 64, NHEAD), 128, ATTN_SMEM_BYTES>>>(qkv, cu, attn);
    // 4. Wo projection + residual(original feats)
    gemm_tc_kernel<1><<<dim3(EMBED / BN, N_TOK / BM), 256, GEMM_SMEM_BYTES>>>(
        attn, wo_a, bo, feats, res1, N_TOK, EMBED, EMBED);
    // 5. LN1 -> h
    layernorm_kernel<<<N_TOK, 256>>>(res1, ln1_g, ln1_b, h);
    // 6. FFN up + gelu
    gemm_tc_kernel<2><<<dim3(FFN / BN, N_TOK / BM), 256, GEMM_SMEM_BYTES>>>(
        h, w1_a, b1, nullptr, ffn, N_TOK, FFN, EMBED);
    // 7. FFN down + residual(h)
    gemm_tc_kernel<1><<<dim3(EMBED / BN, N_TOK / BM), 256, GEMM_SMEM_BYTES>>>(
        ffn, w2_a, b2, h, res1, N_TOK, EMBED, FFN);
    // 8. LN2 -> out
    layernorm_kernel<<<N_TOK, 256>>>(res1, ln2_g, ln2_b, out);
}

// round 14
// speedup vs baseline: 2.0870x; 1.0224x over previous
#include <cuda_runtime.h>
#include <cuda_bf16.h>
#include <math.h>
#include <stdint.h>

#define N_TOK 4096
#define EMBED 1024
#define NHEAD 16
#define HDIM 64
#define FFN 4096
#define QKV3 3072

// ---------------- scratch (device globals; no cudaMalloc allowed) ----------
__device__ alignas(16) float g_qkv[N_TOK * QKV3];
__device__ alignas(16) float g_attn[N_TOK * EMBED];
__device__ alignas(16) float g_res1[N_TOK * EMBED];
__device__ alignas(16) float g_h[N_TOK * EMBED];
__device__ alignas(16) float g_ffn[N_TOK * FFN];
__device__ alignas(16) float g_feats_a[N_TOK * EMBED];
__device__ alignas(16) float g_wqkv[EMBED * QKV3];
__device__ alignas(16) float g_wo[EMBED * EMBED];
__device__ alignas(16) float g_w1[EMBED * FFN];
__device__ alignas(16) float g_w2[FFN * EMBED];

__device__ __forceinline__ uint32_t f2tf32(float x) {
    uint32_t u;
    asm("cvt.rna.tf32.f32 %0, %1;" : "=r"(u) : "f"(x));
    return u;
}

__global__ void copy_tf32_kernel(const float* __restrict__ src,
                                 float* __restrict__ dst, int n) {
    int i = blockIdx.x * blockDim.x + threadIdx.x;
    if (i < n) dst[i] = __uint_as_float(f2tf32(src[i]));
}

// ---------------- TF32 tensor-core GEMM: 128x256 tile, BK=64, 2 stages -----
#define NSTAGE 2
#define BM 128
#define BN 256
#define BK 64
#define ASTRIDE 68     // 64 + 4 pad; %32==4 -> a-read bank (4g+t) conflict-free
#define BSTRIDE 264    // 256 + 8 pad; %32==8 -> b-read bank (8t+g) conflict-free
#define A_TILE (BM * ASTRIDE)
#define B_TILE (BK * BSTRIDE)
#define STAGE_FLOATS (A_TILE + B_TILE)
#define GEMM_SMEM_BYTES (NSTAGE * STAGE_FLOATS * 4)

__device__ __forceinline__ void cp16(uint32_t s, const void* g) {
    asm volatile("cp.async.cg.shared.global [%0], [%1], 16;" :: "r"(s), "l"(g));
}
__device__ __forceinline__ void cp_commit() {
    asm volatile("cp.async.commit_group;");
}

__device__ __forceinline__ void mma_tf32(float* c, const uint32_t* a, const uint32_t* b) {
    asm volatile(
        "mma.sync.aligned.m16n8k8.row.col.f32.tf32.tf32.f32 "
        "{%0,%1,%2,%3}, {%4,%5,%6,%7}, {%8,%9}, {%0,%1,%2,%3};"
        : "+f"(c[0]), "+f"(c[1]), "+f"(c[2]), "+f"(c[3])
        : "r"(a[0]), "r"(a[1]), "r"(a[2]), "r"(a[3]), "r"(b[0]), "r"(b[1]));
}

// EPI: 0 = bias, 1 = bias + resid, 2 = bias + gelu
template <int EPI>
__global__ void __launch_bounds__(256, 1)
gemm_tc_kernel(const float* __restrict__ A, const float* __restrict__ W,
               const float* __restrict__ bias, const float* __restrict__ resid,
               float* __restrict__ C, int M, int N, int K) {
    extern __shared__ float smem[];
    const uint32_t smem_base = (uint32_t)__cvta_generic_to_shared(smem);

    const int tid = threadIdx.x;
    const int wid = tid >> 5;
    const int lane = tid & 31;
    const int g = lane >> 2;
    const int t = lane & 3;
    const int m0 = blockIdx.y * BM;
    const int n0 = blockIdx.x * BN;
    const int wm = (wid & 1) * 64;
    const int wn = (wid >> 1) * 64;

    const int NK = K >> 6;   // K / 64

    auto load_tile = [&](int s, int kt) {
        int k0 = kt * BK;
        uint32_t sb = smem_base + (uint32_t)(s * STAGE_FLOATS) * 4u;
        // A: 128 rows x 64 cols = 2048 float4, 8 per thread
#pragma unroll
        for (int i = 0; i < 8; i++) {
            int idx = tid + i * 256;
            int ar = idx >> 4, ac4 = idx & 15;
            cp16(sb + (uint32_t)(ar * ASTRIDE + ac4 * 4) * 4u,
                 &A[(size_t)(m0 + ar) * K + k0 + ac4 * 4]);
        }
        // B: 64 rows x 256 cols = 4096 float4, 16 per thread
        uint32_t sbB = sb + (uint32_t)A_TILE * 4u;
#pragma unroll
        for (int i = 0; i < 16; i++) {
            int idx = tid + i * 256;
            int br = idx >> 6, bc4 = idx & 63;
            cp16(sbB + (uint32_t)(br * BSTRIDE + bc4 * 4) * 4u,
                 &W[(size_t)(k0 + br) * N + n0 + bc4 * 4]);
        }
        cp_commit();
    };

    float acc[4][8][4];
#pragma unroll
    for (int i = 0; i < 4; i++)
#pragma unroll
        for (int j = 0; j < 8; j++)
#pragma unroll
            for (int r = 0; r < 4; r++) acc[i][j][r] = 0.f;

    load_tile(0, 0);

    for (int k = 0; k < NK; k++) {
        if (k + 1 < NK) {
            load_tile((k + 1) & 1, k + 1);           // overlaps compute(k)
            asm volatile("cp.async.wait_group 1;");  // group k done
        } else {
            asm volatile("cp.async.wait_group 0;");
        }
        __syncthreads();

        const float* As_ = smem + (k & 1) * STAGE_FLOATS;
        const float* Bs_ = As_ + A_TILE;
#pragma unroll
        for (int ks = 0; ks < 8; ks++) {
            uint32_t a[4][4];
#pragma unroll
            for (int mt = 0; mt < 4; mt++) {
                int r = wm + mt * 16 + g;
                int c = ks * 8 + t;
                a[mt][0] = __float_as_uint(As_[r * ASTRIDE + c]);
                a[mt][1] = __float_as_uint(As_[(r + 8) * ASTRIDE + c]);
                a[mt][2] = __float_as_uint(As_[r * ASTRIDE + c + 4]);
                a[mt][3] = __float_as_uint(As_[(r + 8) * ASTRIDE + c + 4]);
            }
            uint32_t b[8][2];
#pragma unroll
            for (int nt = 0; nt < 8; nt++) {
                int c = wn + nt * 8 + g;
                b[nt][0] = __float_as_uint(Bs_[(ks * 8 + t) * BSTRIDE + c]);
                b[nt][1] = __float_as_uint(Bs_[(ks * 8 + t + 4) * BSTRIDE + c]);
            }
#pragma unroll
            for (int mt = 0; mt < 4; mt++)
#pragma unroll
                for (int nt = 0; nt < 8; nt++)
                    mma_tf32(acc[mt][nt], a[mt], b[nt]);
        }
        __syncthreads();
    }

#pragma unroll
    for (int mt = 0; mt < 4; mt++) {
#pragma unroll
        for (int nt = 0; nt < 8; nt++) {
            int r0 = m0 + wm + mt * 16 + g;
            int c0 = n0 + wn + nt * 8 + 2 * t;
#pragma unroll
            for (int half = 0; half < 2; half++) {
                int r = r0 + half * 8;
#pragma unroll
                for (int e = 0; e < 2; e++) {
                    int c = c0 + e;
                    float v = acc[mt][nt][half * 2 + e] + bias[c];
                    if (EPI == 1) v += resid[(size_t)r * N + c];
                    if (EPI == 2) {
                        float x = v;
                        float th = tanhf(0.7978845608028654f *
                                         (x + 0.044715f * x * x * x));
                        v = 0.5f * x * (1.f + th);
                    }
                    C[(size_t)r * N + c] = v;
                }
            }
        }
    }
}

// ---------------- RoPE (in-place on q,k of g_qkv) --------------------------
__global__ void rope_kernel(float* __restrict__ qkv, const float* __restrict__ coords,
                            const float* __restrict__ inv_freq) {
    int n = blockIdx.x;
    __shared__ alignas(16) float cs[32];
    __shared__ alignas(16) float sn[32];
    int t = threadIdx.x;
    if (t < 32) {
        int d = t >> 3, f = t & 7;
        float ang = coords[n * 4 + d] * inv_freq[d * 8 + f];
        cs[t] = cosf(ang);
        sn[t] = sinf(ang);
    }
    __syncthreads();
#pragma unroll
    for (int w = t; w < 1024; w += 256) {
        int qk = w >> 9;
        int h = (w >> 5) & 15;
        int p = w & 31;
        float* base = qkv + (size_t)n * QKV3 + qk * EMBED + h * HDIM;
        float x1 = base[p], x2 = base[p + 32];
        base[p]      = x1 * cs[p] - x2 * sn[p];
        base[p + 32] = x2 * cs[p] + x1 * sn[p];
    }
}

// ---------------- FlashAttention with tf32 mma (R12, unchanged) -------------
#define KS_STRIDE 76
#define VS_STRIDE 72
#define PS_STRIDE 68
#define ATTN_SMEM_FLOATS (64 * KS_STRIDE + 64 * VS_STRIDE + 64 * PS_STRIDE)
#define ATTN_SMEM_BYTES (ATTN_SMEM_FLOATS * 4)

__global__ void __launch_bounds__(128, 1)
attn_mma_kernel(const float* __restrict__ qkv, const int* __restrict__ cu,
                float* __restrict__ out) {
    extern __shared__ float asmem[];
    float* Ks = asmem;
    float* Vs = Ks + 64 * KS_STRIDE;
    float* Ps = Vs + 64 * VS_STRIDE;
    __shared__ int kst[64], ken[64];

    const int h = blockIdx.y;
    const int qb = blockIdx.x * 64;
    const int tid = threadIdx.x;
    const int wid = tid >> 5;
    const int lane = tid & 31;
    const int g = lane >> 2;
    const int t = lane & 3;
    const int r0 = wid * 16 + g;
    const int r1 = r0 + 8;

    if (tid < 64) {
        int qi = qb + tid;
        int s = 0;
#pragma unroll
        for (int i = 1; i <= 7; i++)
            if (cu[i] <= qi) s = i;
        kst[tid] = cu[s];
        ken[tid] = cu[s + 1];
    }
    __syncthreads();
    const int kb0 = kst[0] & ~63;
    const int keM = ken[63];
    const int ks0 = kst[r0], ke0 = ken[r0];
    const int ks1 = kst[r1], ke1 = ken[r1];

    uint32_t qf[8][4];
    {
        const float* q0 = qkv + (size_t)(qb + r0) * QKV3 + h * HDIM;
        const float* q1 = qkv + (size_t)(qb + r1) * QKV3 + h * HDIM;
#pragma unroll
        for (int ks = 0; ks < 8; ks++) {
            qf[ks][0] = __float_as_uint(q0[ks * 8 + t] * 0.125f);
            qf[ks][1] = __float_as_uint(q1[ks * 8 + t] * 0.125f);
            qf[ks][2] = __float_as_uint(q0[ks * 8 + t + 4] * 0.125f);
            qf[ks][3] = __float_as_uint(q1[ks * 8 + t + 4] * 0.125f);
        }
    }

    float O[8][4];
#pragma unroll
    for (int nt = 0; nt < 8; nt++)
#pragma unroll
        for (int e = 0; e < 4; e++) O[nt][e] = 0.f;
    float m0 = -1e30f, m1 = -1e30f, l0 = 0.f, l1 = 0.f;

    for (int kt = kb0; kt < keM; kt += 64) {
        __syncthreads();
        {
            int row = tid >> 1, cb = (tid & 1) * 32;
            const float* kp = qkv + (size_t)(kt + row) * QKV3 + EMBED + h * HDIM + cb;
            const float* vp = qkv + (size_t)(kt + row) * QKV3 + 2 * EMBED + h * HDIM + cb;
            float4* kd = (float4*)&Ks[row * KS_STRIDE + cb];
            float4* vd = (float4*)&Vs[row * VS_STRIDE + cb];
#pragma unroll
            for (int d4 = 0; d4 < 8; d4++) {
                kd[d4] = ((const float4*)kp)[d4];
                vd[d4] = ((const float4*)vp)[d4];
            }
        }
        __syncthreads();

        float S[8][4];
#pragma unroll
        for (int nt = 0; nt < 8; nt++)
#pragma unroll
            for (int e = 0; e < 4; e++) S[nt][e] = 0.f;
#pragma unroll
        for (int ks = 0; ks < 8; ks++) {
#pragma unroll
            for (int nt = 0; nt < 8; nt++) {
                uint32_t b[2];
                b[0] = __float_as_uint(Ks[(nt * 8 + g) * KS_STRIDE + ks * 8 + t]);
                b[1] = __float_as_uint(Ks[(nt * 8 + g) * KS_STRIDE + ks * 8 + t + 4]);
                mma_tf32(S[nt], qf[ks], b);
            }
        }

        float cm0 = -1e30f, cm1 = -1e30f;
#pragma unroll
        for (int nt = 0; nt < 8; nt++) {
            int c0 = kt + nt * 8 + 2 * t;
            int c1 = c0 + 1;
            S[nt][0] = (c0 >= ks0 && c0 < ke0) ? S[nt][0] : -1e30f;
            S[nt][1] = (c1 >= ks0 && c1 < ke0) ? S[nt][1] : -1e30f;
            S[nt][2] = (c0 >= ks1 && c0 < ke1) ? S[nt][2] : -1e30f;
            S[nt][3] = (c1 >= ks1 && c1 < ke1) ? S[nt][3] : -1e30f;
            cm0 = fmaxf(cm0, fmaxf(S[nt][0], S[nt][1]));
            cm1 = fmaxf(cm1, fmaxf(S[nt][2], S[nt][3]));
        }
        cm0 = fmaxf(cm0, __shfl_xor_sync(0xffffffffu, cm0, 1));
        cm0 = fmaxf(cm0, __shfl_xor_sync(0xffffffffu, cm0, 2));
        cm1 = fmaxf(cm1, __shfl_xor_sync(0xffffffffu, cm1, 1));
        cm1 = fmaxf(cm1, __shfl_xor_sync(0xffffffffu, cm1, 2));
        float mn0 = fmaxf(m0, cm0);
        float mn1 = fmaxf(m1, cm1);
        float sc0 = __expf(m0 - mn0);
        float sc1 = __expf(m1 - mn1);

        float ps0 = 0.f, ps1 = 0.f;
#pragma unroll
        for (int nt = 0; nt < 8; nt++) {
            float p00 = (S[nt][0] > -1e29f) ? __expf(S[nt][0] - mn0) : 0.f;
            float p01 = (S[nt][1] > -1e29f) ? __expf(S[nt][1] - mn0) : 0.f;
            float p10 = (S[nt][2] > -1e29f) ? __expf(S[nt][2] - mn1) : 0.f;
            float p11 = (S[nt][3] > -1e29f) ? __expf(S[nt][3] - mn1) : 0.f;
            ps0 += p00 + p01;
            ps1 += p10 + p11;
            Ps[r0 * PS_STRIDE + nt * 8 + 2 * t]     = p00;
            Ps[r0 * PS_STRIDE + nt * 8 + 2 * t + 1] = p01;
            Ps[r1 * PS_STRIDE + nt * 8 + 2 * t]     = p10;
            Ps[r1 * PS_STRIDE + nt * 8 + 2 * t + 1] = p11;
            O[nt][0] *= sc0; O[nt][1] *= sc0;
            O[nt][2] *= sc1; O[nt][3] *= sc1;
        }
        ps0 += __shfl_xor_sync(0xffffffffu, ps0, 1);
        ps0 += __shfl_xor_sync(0xffffffffu, ps0, 2);
        ps1 += __shfl_xor_sync(0xffffffffu, ps1, 1);
        ps1 += __shfl_xor_sync(0xffffffffu, ps1, 2);
        l0 = l0 * sc0 + ps0;
        l1 = l1 * sc1 + ps1;
        m0 = mn0; m1 = mn1;
        __syncwarp();

#pragma unroll
        for (int ks2 = 0; ks2 < 8; ks2++) {
            uint32_t pa[4];
            pa[0] = __float_as_uint(Ps[r0 * PS_STRIDE + ks2 * 8 + t]);
            pa[1] = __float_as_uint(Ps[r1 * PS_STRIDE + ks2 * 8 + t]);
            pa[2] = __float_as_uint(Ps[r0 * PS_STRIDE + ks2 * 8 + t + 4]);
            pa[3] = __float_as_uint(Ps[r1 * PS_STRIDE + ks2 * 8 + t + 4]);
#pragma unroll
            for (int nt = 0; nt < 8; nt++) {
                uint32_t vb[2];
                vb[0] = __float_as_uint(Vs[(ks2 * 8 + t) * VS_STRIDE + nt * 8 + g]);
                vb[1] = __float_as_uint(Vs[(ks2 * 8 + t + 4) * VS_STRIDE + nt * 8 + g]);
                mma_tf32(O[nt], pa, vb);
            }
        }
        __syncwarp();
    }

    float il0 = 1.f / l0, il1 = 1.f / l1;
    float* o0 = out + (size_t)(qb + r0) * EMBED + h * HDIM;
    float* o1 = out + (size_t)(qb + r1) * EMBED + h * HDIM;
#pragma unroll
    for (int nt = 0; nt < 8; nt++) {
        o0[nt * 8 + 2 * t]     = O[nt][0] * il0;
        o0[nt * 8 + 2 * t + 1] = O[nt][1] * il0;
        o1[nt * 8 + 2 * t]     = O[nt][2] * il1;
        o1[nt * 8 + 2 * t + 1] = O[nt][3] * il1;
    }
}

// ---------------- LayerNorm ------------------------------------------------
__device__ __forceinline__ float blockReduceSum(float v) {
    __shared__ alignas(16) float red[8];
    int lane = threadIdx.x & 31, wid = threadIdx.x >> 5;
#pragma unroll
    for (int off = 16; off; off >>= 1) v += __shfl_xor_sync(0xffffffffu, v, off);
    __syncthreads();
    if (lane == 0) red[wid] = v;
    __syncthreads();
    v = (threadIdx.x < 8) ? red[threadIdx.x] : 0.f;
    if (wid == 0) {
#pragma unroll
        for (int off = 4; off; off >>= 1) v += __shfl_xor_sync(0xffu, v, off);
        if (lane == 0) red[0] = v;
    }
    __syncthreads();
    return red[0];
}

__global__ void __launch_bounds__(256)
layernorm_kernel(const float* __restrict__ x, const float* __restrict__ g,
                 const float* __restrict__ b, float* __restrict__ y) {
    int row = blockIdx.x;
    int t = threadIdx.x;
    const float4* xr = (const float4*)(x + (size_t)row * EMBED);
    float4 v = xr[t];
    float s = (v.x + v.y) + (v.z + v.w);
    float mean = blockReduceSum(s) * (1.f / 1024.f);
    float dx = v.x - mean, dy = v.y - mean, dz = v.z - mean, dw = v.w - mean;
    float sq = dx * dx + dy * dy + dz * dz + dw * dw;
    float var = blockReduceSum(sq) * (1.f / 1024.f);
    float rstd = rsqrtf(var + 1e-5f);
    int c = t * 4;
    float g0 = g[c], g1 = g[c + 1], g2 = g[c + 2], g3 = g[c + 3];
    float b0 = b[c], b1 = b[c + 1], b2 = b[c + 2], b3 = b[c + 3];
    float* yr = y + (size_t)row * EMBED + c;
    yr[0] = dx * rstd * g0 + b0;
    yr[1] = dy * rstd * g1 + b1;
    yr[2] = dz * rstd * g2 + b2;
    yr[3] = dw * rstd * g3 + b3;
}

// ---------------- launch ---------------------------------------------------
extern "C" void kernel_launch(void* const* d_in, const int* in_sizes, int n_in,
                              void* d_out, int out_size) {
    const float* coords   = (const float*)d_in[0];
    const float* feats    = (const float*)d_in[1];
    const int*   cu       = (const int*)d_in[2];
    const float* Wqkv     = (const float*)d_in[3];
    const float* bqkv     = (const float*)d_in[4];
    const float* Wo       = (const float*)d_in[5];
    const float* bo       = (const float*)d_in[6];
    const float* inv_freq = (const float*)d_in[7];
    const float* ln1_g    = (const float*)d_in[8];
    const float* ln1_b    = (const float*)d_in[9];
    const float* W1       = (const float*)d_in[10];
    const float* b1       = (const float*)d_in[11];
    const float* W2       = (const float*)d_in[12];
    const float* b2       = (const float*)d_in[13];
    const float* ln2_g    = (const float*)d_in[14];
    const float* ln2_b    = (const float*)d_in[15];
    float* out = (float*)d_out;

    float *qkv, *attn, *res1, *h, *ffn;
    float *feats_a, *wqkv_a, *wo_a, *w1_a, *w2_a;
    cudaGetSymbolAddress((void**)&qkv, g_qkv);
    cudaGetSymbolAddress((void**)&attn, g_attn);
    cudaGetSymbolAddress((void**)&res1, g_res1);
    cudaGetSymbolAddress((void**)&h, g_h);
    cudaGetSymbolAddress((void**)&ffn, g_ffn);
    cudaGetSymbolAddress((void**)&feats_a, g_feats_a);
    cudaGetSymbolAddress((void**)&wqkv_a, g_wqkv);
    cudaGetSymbolAddress((void**)&wo_a, g_wo);
    cudaGetSymbolAddress((void**)&w1_a, g_w1);
    cudaGetSymbolAddress((void**)&w2_a, g_w2);

    cudaFuncSetAttribute(gemm_tc_kernel<0>,
                         cudaFuncAttributeMaxDynamicSharedMemorySize, GEMM_SMEM_BYTES);
    cudaFuncSetAttribute(gemm_tc_kernel<1>,
                         cudaFuncAttributeMaxDynamicSharedMemorySize, GEMM_SMEM_BYTES);
    cudaFuncSetAttribute(gemm_tc_kernel<2>,
                         cudaFuncAttributeMaxDynamicSharedMemorySize, GEMM_SMEM_BYTES);
    cudaFuncSetAttribute(attn_mma_kernel,
                         cudaFuncAttributeMaxDynamicSharedMemorySize, ATTN_SMEM_BYTES);

    // 0. align + tf32-round unaligned inputs
    copy_tf32_kernel<<<(N_TOK * EMBED) / 256, 256>>>(feats, feats_a, N_TOK * EMBED);
    copy_tf32_kernel<<<(EMBED * QKV3) / 256, 256>>>(Wqkv, wqkv_a, EMBED * QKV3);
    copy_tf32_kernel<<<(EMBED * EMBED) / 256, 256>>>(Wo, wo_a, EMBED * EMBED);
    copy_tf32_kernel<<<(EMBED * FFN) / 256, 256>>>(W1, w1_a, EMBED * FFN);
    copy_tf32_kernel<<<(FFN * EMBED) / 256, 256>>>(W2, w2_a, FFN * EMBED);

    // 1. QKV projection
    gemm_tc_kernel<0><<<dim3(QKV3 / BN, N_TOK / BM), 256, GEMM_SMEM_BYTES>>>(
        feats_a, wqkv_a, bqkv, nullptr, qkv, N_TOK, QKV3, EMBED);
    // 2. RoPE on q,k
    rope_kernel<<<N_TOK, 256>>>(qkv, coords, inv_freq);
    // 3. FlashAttention (tf32 mma)
    attn_mma_kernel<<<dim3(N_TOK / 64, NHEAD), 128, ATTN_SMEM_BYTES>>>(qkv, cu, attn);
    // 4. Wo projection + residual(original feats)
    gemm_tc_kernel<1><<<dim3(EMBED / BN, N_TOK / BM), 256, GEMM_SMEM_BYTES>>>(
        attn, wo_a, bo, feats, res1, N_TOK, EMBED, EMBED);
    // 5. LN1 -> h
    layernorm_kernel<<<N_TOK, 256>>>(res1, ln1_g, ln1_b, h);
    // 6. FFN up + gelu
    gemm_tc_kernel<2><<<dim3(FFN / BN, N_TOK / BM), 256, GEMM_SMEM_BYTES>>>(
        h, w1_a, b1, nullptr, ffn, N_TOK, FFN, EMBED);
    // 7. FFN down + residual(h)
    gemm_tc_kernel<1><<<dim3(EMBED / BN, N_TOK / BM), 256, GEMM_SMEM_BYTES>>>(
        ffn, w2_a, b2, h, res1, N_TOK, EMBED, FFN);
    // 8. LN2 -> out
    layernorm_kernel<<<N_TOK, 256>>>(res1, ln2_g, ln2_b, out);
}